// round 2
// baseline (speedup 1.0000x reference)
#include <cuda_runtime.h>

// ---------------------------------------------------------------------------
// MultiHeadAttention: out = softmax_causal((xWq)(xWk)^T/sqrt(64)) (xWv) Wo + bo
// B=2, S=2048, D=1024, H=16, Dh=64.  All fp32 (round-0 correctness-safe path).
// Pipeline: qkv_gemm -> attn_kernel (flash, online softmax) -> out_gemm
// ---------------------------------------------------------------------------

#define D_MODEL 1024
#define SEQ     2048
#define BATCH   2
#define NHEAD   16
#define HDIM    64

// Scratch (device globals; no allocation allowed)
__device__ float g_q[BATCH * NHEAD * SEQ * HDIM];
__device__ float g_k[BATCH * NHEAD * SEQ * HDIM];
__device__ float g_v[BATCH * NHEAD * SEQ * HDIM];
__device__ float g_ctx[BATCH * SEQ * D_MODEL];

// ---------------------------------------------------------------------------
// Tiled fp32 GEMM: C[4096x1024] = A[4096x1024] @ W[1024x1024]
// BM=BN=128, BK=32, 256 threads, 8x8 micro-tile per thread.
// qkv variant scatters outputs into [B,H,S,Dh] layout for q/k/v.
// ---------------------------------------------------------------------------
__global__ __launch_bounds__(256, 2) void qkv_gemm(
    const float* __restrict__ X,
    const float* __restrict__ Wq,
    const float* __restrict__ Wk,
    const float* __restrict__ Wv)
{
    __shared__ float As[128 * 32];   // [row][k] row-major
    __shared__ float Bs[32 * 128];   // [k][n]  row-major

    const float* W = (blockIdx.z == 0) ? Wq : ((blockIdx.z == 1) ? Wk : Wv);
    float* dst     = (blockIdx.z == 0) ? g_q : ((blockIdx.z == 1) ? g_k : g_v);

    const int m0 = blockIdx.y * 128;
    const int n0 = blockIdx.x * 128;
    const int tid = threadIdx.x;
    const int tx = tid & 15;      // 16 col groups
    const int ty = tid >> 4;      // 16 row groups

    float acc[8][8];
#pragma unroll
    for (int i = 0; i < 8; i++)
#pragma unroll
        for (int j = 0; j < 8; j++) acc[i][j] = 0.f;

    for (int k0 = 0; k0 < D_MODEL; k0 += 32) {
#pragma unroll
        for (int i = 0; i < 4; i++) {
            int f = i * 256 + tid;
            int arow = f >> 3, akq = f & 7;   // 8 float4 per 32-float A row
            *(float4*)&As[arow * 32 + akq * 4] =
                *(const float4*)&X[(size_t)(m0 + arow) * D_MODEL + k0 + akq * 4];
            int brow = f >> 5, bn4 = f & 31;  // 32 float4 per 128-float B row
            *(float4*)&Bs[brow * 128 + bn4 * 4] =
                *(const float4*)&W[(size_t)(k0 + brow) * D_MODEL + n0 + bn4 * 4];
        }
        __syncthreads();
#pragma unroll
        for (int kk = 0; kk < 32; kk++) {
            float a[8], b[8];
#pragma unroll
            for (int i = 0; i < 8; i++) a[i] = As[(ty * 8 + i) * 32 + kk];  // broadcast
            *(float4*)&b[0] = *(float4*)&Bs[kk * 128 + tx * 4];        // conflict-free
            *(float4*)&b[4] = *(float4*)&Bs[kk * 128 + 64 + tx * 4];   // conflict-free
#pragma unroll
            for (int i = 0; i < 8; i++)
#pragma unroll
                for (int j = 0; j < 8; j++) acc[i][j] = fmaf(a[i], b[j], acc[i][j]);
        }
        __syncthreads();
    }

    // Scatter to [B,H,S,Dh]
#pragma unroll
    for (int i = 0; i < 8; i++) {
        int row = m0 + ty * 8 + i;
        int bb = row >> 11;              // /SEQ
        int ss = row & (SEQ - 1);
#pragma unroll
        for (int j = 0; j < 8; j++) {
            int col = n0 + ((j < 4) ? (tx * 4 + j) : (64 + tx * 4 + (j - 4)));
            int h = col >> 6, d = col & 63;
            dst[((((size_t)bb * NHEAD + h) * SEQ) + ss) * HDIM + d] = acc[i][j];
        }
    }
}

// ---------------------------------------------------------------------------
// Output projection: out = g_ctx @ Wo + bo
// ---------------------------------------------------------------------------
__global__ __launch_bounds__(256, 2) void out_gemm(
    const float* __restrict__ Wo,
    const float* __restrict__ bo,
    float* __restrict__ out)
{
    __shared__ float As[128 * 32];
    __shared__ float Bs[32 * 128];

    const int m0 = blockIdx.y * 128;
    const int n0 = blockIdx.x * 128;
    const int tid = threadIdx.x;
    const int tx = tid & 15;
    const int ty = tid >> 4;

    float acc[8][8];
#pragma unroll
    for (int i = 0; i < 8; i++)
#pragma unroll
        for (int j = 0; j < 8; j++) acc[i][j] = 0.f;

    for (int k0 = 0; k0 < D_MODEL; k0 += 32) {
#pragma unroll
        for (int i = 0; i < 4; i++) {
            int f = i * 256 + tid;
            int arow = f >> 3, akq = f & 7;
            *(float4*)&As[arow * 32 + akq * 4] =
                *(const float4*)&g_ctx[(size_t)(m0 + arow) * D_MODEL + k0 + akq * 4];
            int brow = f >> 5, bn4 = f & 31;
            *(float4*)&Bs[brow * 128 + bn4 * 4] =
                *(const float4*)&Wo[(size_t)(k0 + brow) * D_MODEL + n0 + bn4 * 4];
        }
        __syncthreads();
#pragma unroll
        for (int kk = 0; kk < 32; kk++) {
            float a[8], b[8];
#pragma unroll
            for (int i = 0; i < 8; i++) a[i] = As[(ty * 8 + i) * 32 + kk];
            *(float4*)&b[0] = *(float4*)&Bs[kk * 128 + tx * 4];
            *(float4*)&b[4] = *(float4*)&Bs[kk * 128 + 64 + tx * 4];
#pragma unroll
            for (int i = 0; i < 8; i++)
#pragma unroll
                for (int j = 0; j < 8; j++) acc[i][j] = fmaf(a[i], b[j], acc[i][j]);
        }
        __syncthreads();
    }

#pragma unroll
    for (int i = 0; i < 8; i++) {
        int row = m0 + ty * 8 + i;
#pragma unroll
        for (int j = 0; j < 8; j++) {
            int col = n0 + ((j < 4) ? (tx * 4 + j) : (64 + tx * 4 + (j - 4)));
            out[(size_t)row * D_MODEL + col] = acc[i][j] + bo[col];
        }
    }
}

// ---------------------------------------------------------------------------
// Flash attention (causal), fp32.  One CTA per (b, h, 64-row q-tile).
// 256 threads as 16x16; each thread owns a 4x4 micro-tile of S and of O.
// K is transposed in shared (KsT[d][c]) so both GEMM phases read conflict-free
// LDS.128.  Online softmax with row stats in shared.
// ---------------------------------------------------------------------------
#define LDP 68   // padded row stride (floats)

__global__ __launch_bounds__(256, 2) void attn_kernel()
{
    extern __shared__ float smdyn[];
    float* Qs  = smdyn;              // [r][d]  64*LDP
    float* KsT = Qs + 64 * LDP;      // [d][c]  64*LDP
    float* Vs  = KsT + 64 * LDP;     // [c][d]  64*LDP
    float* Ps  = Vs + 64 * LDP;      // [r][c]  64*LDP (also K-load staging)
    float* red = Ps + 64 * LDP;      // [64][17]
    float* mrow = red + 64 * 17;     // [64]
    float* lrow = mrow + 64;         // [64]

    const int qt = blockIdx.x;       // 0..31
    const int h  = blockIdx.y;
    const int b  = blockIdx.z;
    const int tid = threadIdx.x;
    const int tx = tid & 15;
    const int ty = tid >> 4;

    const size_t headrow = ((size_t)b * NHEAD + h) * SEQ;

    // Load Q tile (64 x 64)
#pragma unroll
    for (int i = 0; i < 4; i++) {
        int f = i * 256 + tid;
        int r = f >> 4, c4 = f & 15;
        *(float4*)&Qs[r * LDP + c4 * 4] =
            *(const float4*)&g_q[(headrow + (size_t)qt * 64 + r) * HDIM + c4 * 4];
    }
    if (tid < 64) { mrow[tid] = -1e30f; lrow[tid] = 0.f; }

    float O[4][4];
#pragma unroll
    for (int i = 0; i < 4; i++)
#pragma unroll
        for (int j = 0; j < 4; j++) O[i][j] = 0.f;

    for (int kt = 0; kt <= qt; kt++) {
        __syncthreads();   // A: prev-iter consumers of Ps/Vs/KsT done; Qs/stat init done

        // Load K tile -> Ps (staging, row-major), V tile -> Vs
#pragma unroll
        for (int i = 0; i < 4; i++) {
            int f = i * 256 + tid;
            int r = f >> 4, c4 = f & 15;
            size_t grow = headrow + (size_t)kt * 64 + r;
            *(float4*)&Ps[r * LDP + c4 * 4] = *(const float4*)&g_k[grow * HDIM + c4 * 4];
            *(float4*)&Vs[r * LDP + c4 * 4] = *(const float4*)&g_v[grow * HDIM + c4 * 4];
        }
        __syncthreads();   // B

        // Transpose staged K into KsT[d][c]
        {
            int c = tid & 63, dg = tid >> 6;
#pragma unroll
            for (int dd = 0; dd < 16; dd++) {
                int d = dg * 16 + dd;
                KsT[d * LDP + c] = Ps[c * LDP + d];
            }
        }
        __syncthreads();   // C

        // S = Q K^T  (rows r = ty*4+i, cols c = tx*4+j)
        float s[4][4];
#pragma unroll
        for (int i = 0; i < 4; i++)
#pragma unroll
            for (int j = 0; j < 4; j++) s[i][j] = 0.f;

#pragma unroll
        for (int d4 = 0; d4 < 16; d4++) {
            float qreg[4][4];
#pragma unroll
            for (int i = 0; i < 4; i++)
                *(float4*)&qreg[i][0] = *(float4*)&Qs[(ty * 4 + i) * LDP + d4 * 4];
#pragma unroll
            for (int dd = 0; dd < 4; dd++) {
                float kreg[4];
                *(float4*)&kreg[0] = *(float4*)&KsT[(d4 * 4 + dd) * LDP + tx * 4];
#pragma unroll
                for (int i = 0; i < 4; i++)
#pragma unroll
                    for (int j = 0; j < 4; j++)
                        s[i][j] = fmaf(qreg[i][dd], kreg[j], s[i][j]);
            }
        }

        // scale + causal mask (only needed on diagonal tile)
#pragma unroll
        for (int i = 0; i < 4; i++)
#pragma unroll
            for (int j = 0; j < 4; j++) s[i][j] *= 0.125f;
        if (kt == qt) {
#pragma unroll
            for (int i = 0; i < 4; i++)
#pragma unroll
                for (int j = 0; j < 4; j++)
                    if ((tx * 4 + j) > (ty * 4 + i)) s[i][j] = -1e30f;
        }

        // row max across tx
#pragma unroll
        for (int i = 0; i < 4; i++) {
            float lm = fmaxf(fmaxf(s[i][0], s[i][1]), fmaxf(s[i][2], s[i][3]));
            red[(ty * 4 + i) * 17 + tx] = lm;
        }
        __syncthreads();   // D

        float nm[4], alpha[4], lsum[4];
#pragma unroll
        for (int i = 0; i < 4; i++) {
            int r = ty * 4 + i;
            float m = -1e30f;
#pragma unroll
            for (int t = 0; t < 16; t++) m = fmaxf(m, red[r * 17 + t]);
            float mo = mrow[r];
            nm[i] = fmaxf(mo, m);
            alpha[i] = __expf(mo - nm[i]);
            float sum = 0.f;
#pragma unroll
            for (int j = 0; j < 4; j++) {
                float p = __expf(s[i][j] - nm[i]);
                s[i][j] = p;
                sum += p;
            }
            lsum[i] = sum;
        }
        __syncthreads();   // E: red reuse; all mrow reads complete

#pragma unroll
        for (int i = 0; i < 4; i++) {
            red[(ty * 4 + i) * 17 + tx] = lsum[i];
            *(float4*)&Ps[(ty * 4 + i) * LDP + tx * 4] = *(float4*)&s[i][0];
        }
        __syncthreads();   // F: sums + P visible

#pragma unroll
        for (int i = 0; i < 4; i++) {
            int r = ty * 4 + i;
            if (tx == 0) {
                float lt = 0.f;
#pragma unroll
                for (int t = 0; t < 16; t++) lt += red[r * 17 + t];
                lrow[r] = lrow[r] * alpha[i] + lt;
                mrow[r] = nm[i];
            }
#pragma unroll
            for (int j = 0; j < 4; j++) O[i][j] *= alpha[i];
        }

        // O += P @ V   (rows r = ty*4+i, cols d = tx*4+j)
#pragma unroll
        for (int c4 = 0; c4 < 16; c4++) {
            float preg[4][4];
#pragma unroll
            for (int i = 0; i < 4; i++)
                *(float4*)&preg[i][0] = *(float4*)&Ps[(ty * 4 + i) * LDP + c4 * 4];
#pragma unroll
            for (int cc = 0; cc < 4; cc++) {
                float vreg[4];
                *(float4*)&vreg[0] = *(float4*)&Vs[(c4 * 4 + cc) * LDP + tx * 4];
#pragma unroll
                for (int i = 0; i < 4; i++)
#pragma unroll
                    for (int j = 0; j < 4; j++)
                        O[i][j] = fmaf(preg[i][cc], vreg[j], O[i][j]);
            }
        }
    }

    __syncthreads();  // final lrow/mrow writes visible

    // Normalize and write ctx in [B,S,D] layout
#pragma unroll
    for (int i = 0; i < 4; i++) {
        int r = ty * 4 + i;
        float inv = 1.f / lrow[r];
        float4 o;
        o.x = O[i][0] * inv; o.y = O[i][1] * inv;
        o.z = O[i][2] * inv; o.w = O[i][3] * inv;
        size_t srow = (size_t)b * SEQ + (size_t)qt * 64 + r;
        *(float4*)&g_ctx[srow * D_MODEL + h * 64 + tx * 4] = o;
    }
}

#define ATTN_SMEM ((4 * 64 * LDP + 64 * 17 + 128) * (int)sizeof(float))

// ---------------------------------------------------------------------------
extern "C" void kernel_launch(void* const* d_in, const int* in_sizes, int n_in,
                              void* d_out, int out_size)
{
    const float* x  = (const float*)d_in[0];
    const float* wq = (const float*)d_in[1];
    const float* wk = (const float*)d_in[2];
    const float* wv = (const float*)d_in[3];
    const float* wo = (const float*)d_in[4];
    const float* bo = (const float*)d_in[5];
    float* out = (float*)d_out;

    cudaFuncSetAttribute(attn_kernel,
                         cudaFuncAttributeMaxDynamicSharedMemorySize, ATTN_SMEM);

    qkv_gemm<<<dim3(8, 32, 3), 256>>>(x, wq, wk, wv);
    attn_kernel<<<dim3(32, NHEAD, BATCH), 256, ATTN_SMEM>>>();
    out_gemm<<<dim3(8, 32), 256>>>(wo, bo, out);
}

// round 11
// speedup vs baseline: 1.5597x; 1.5597x over previous
#include <cuda_runtime.h>
#include <cuda_bf16.h>
#include <cstdint>

// ---------------------------------------------------------------------------
// MultiHeadAttention: out = softmax_causal((xWq)(xWk)^T/sqrt(64)) (xWv) Wo + bo
// B=2, S=2048, D=1024, H=16, Dh=64.
// Round 10: identical resubmission of round 7/8/9 (broker timeouts).
// Projection GEMMs on baseline mma.sync.m16n8k16 bf16 (HMMA; compute_103
// target rejects tcgen05), 2-way bf16 split with 3 products, fp32 register
// accumulators, cp.async double buffering.  Attention fp32 flash (known good).
// ---------------------------------------------------------------------------

#define D_MODEL 1024
#define SEQ     2048
#define BATCH   2
#define NHEAD   16
#define HDIM    64

// ---------------- scratch (device globals; no allocation allowed) ----------
__device__ float g_q[BATCH * NHEAD * SEQ * HDIM];
__device__ float g_k[BATCH * NHEAD * SEQ * HDIM];
__device__ float g_v[BATCH * NHEAD * SEQ * HDIM];
__device__ float g_ctx[BATCH * SEQ * D_MODEL];

__device__ __nv_bfloat16 g_xhi[BATCH * SEQ * D_MODEL];
__device__ __nv_bfloat16 g_xlo[BATCH * SEQ * D_MODEL];
__device__ __nv_bfloat16 g_chi[BATCH * SEQ * D_MODEL];
__device__ __nv_bfloat16 g_clo[BATCH * SEQ * D_MODEL];
// transposed weights [n][k], 4 slots: wq, wk, wv, wo
__device__ __nv_bfloat16 g_wt_hi[4 * D_MODEL * D_MODEL];
__device__ __nv_bfloat16 g_wt_lo[4 * D_MODEL * D_MODEL];

// ---------------- PTX helpers (all baseline sm_80+ features) ----------------
__device__ __forceinline__ uint32_t smem_u32(const void* p) {
    uint32_t a;
    asm("{ .reg .u64 t; cvta.to.shared.u64 t, %1; cvt.u32.u64 %0, t; }"
        : "=r"(a) : "l"(p));
    return a;
}
__device__ __forceinline__ void ldm4(uint32_t* r, uint32_t addr) {
    asm volatile("ldmatrix.sync.aligned.m8n8.x4.shared.b16 {%0,%1,%2,%3}, [%4];"
                 : "=r"(r[0]), "=r"(r[1]), "=r"(r[2]), "=r"(r[3]) : "r"(addr));
}
__device__ __forceinline__ void mma16816(float* c, const uint32_t* a,
                                         uint32_t b0, uint32_t b1) {
    asm volatile("mma.sync.aligned.m16n8k16.row.col.f32.bf16.bf16.f32 "
                 "{%0,%1,%2,%3}, {%4,%5,%6,%7}, {%8,%9}, {%0,%1,%2,%3};"
                 : "+f"(c[0]), "+f"(c[1]), "+f"(c[2]), "+f"(c[3])
                 : "r"(a[0]), "r"(a[1]), "r"(a[2]), "r"(a[3]), "r"(b0), "r"(b1));
}
__device__ __forceinline__ void cpasync16(uint32_t dst, const void* src) {
    asm volatile("cp.async.cg.shared.global [%0], [%1], 16;" :: "r"(dst), "l"(src));
}
#define CP_COMMIT() asm volatile("cp.async.commit_group;" ::: "memory")
#define CP_WAIT(n)  asm volatile("cp.async.wait_group %0;" :: "n"(n) : "memory")

// ---------------- conversion kernels ----------------------------------------
__global__ void conv_split(const float* __restrict__ src,
                           __nv_bfloat16* __restrict__ hi,
                           __nv_bfloat16* __restrict__ lo)
{
    int i = (blockIdx.x * blockDim.x + threadIdx.x) * 4;
    float4 v = *(const float4*)(src + i);
    __nv_bfloat16 h0 = __float2bfloat16_rn(v.x), h1 = __float2bfloat16_rn(v.y);
    __nv_bfloat16 h2 = __float2bfloat16_rn(v.z), h3 = __float2bfloat16_rn(v.w);
    __nv_bfloat16 l0 = __float2bfloat16_rn(v.x - __bfloat162float(h0));
    __nv_bfloat16 l1 = __float2bfloat16_rn(v.y - __bfloat162float(h1));
    __nv_bfloat16 l2 = __float2bfloat16_rn(v.z - __bfloat162float(h2));
    __nv_bfloat16 l3 = __float2bfloat16_rn(v.w - __bfloat162float(h3));
    *(__nv_bfloat162*)(hi + i)     = __halves2bfloat162(h0, h1);
    *(__nv_bfloat162*)(hi + i + 2) = __halves2bfloat162(h2, h3);
    *(__nv_bfloat162*)(lo + i)     = __halves2bfloat162(l0, l1);
    *(__nv_bfloat162*)(lo + i + 2) = __halves2bfloat162(l2, l3);
}

// transpose + split weights: Wt[n][k] = split(W[k][n]); z picks wq/wk/wv/wo
__global__ void conv_wt(const float* __restrict__ wq, const float* __restrict__ wk,
                        const float* __restrict__ wv, const float* __restrict__ wo)
{
    __shared__ float t[32][33];
    int z = blockIdx.z;
    const float* W = (z == 0) ? wq : (z == 1) ? wk : (z == 2) ? wv : wo;
    __nv_bfloat16* Hi = g_wt_hi + (size_t)z * D_MODEL * D_MODEL;
    __nv_bfloat16* Lo = g_wt_lo + (size_t)z * D_MODEL * D_MODEL;
    int k0 = blockIdx.y * 32, n0 = blockIdx.x * 32;
    int tx = threadIdx.x, ty = threadIdx.y;   // 32 x 8
#pragma unroll
    for (int i = 0; i < 4; i++)
        t[ty + i * 8][tx] = W[(size_t)(k0 + ty + i * 8) * D_MODEL + n0 + tx];
    __syncthreads();
#pragma unroll
    for (int i = 0; i < 4; i++) {
        int n = n0 + ty + i * 8, k = k0 + tx;
        float v = t[tx][ty + i * 8];
        __nv_bfloat16 h = __float2bfloat16_rn(v);
        __nv_bfloat16 l = __float2bfloat16_rn(v - __bfloat162float(h));
        Hi[(size_t)n * D_MODEL + k] = h;
        Lo[(size_t)n * D_MODEL + k] = l;
    }
}

// ---------------- mma.sync GEMM ----------------------------------------------
// C[4096 x 1024] = A[m][k] @ Wt[n][k]^T, 128x128 tile/CTA, BK=32,
// cp.async double buffer, bf16 split: D = Ahi*Bhi + Ahi*Blo + Alo*Bhi.
// 8 warps as 4(m) x 2(n); warp tile 32x64; mma.sync m16n8k16 .row.col.
// mode 0: qkv (z selects weight slot + q/k/v dst, scatter [B,H,S,Dh])
// mode 1: out-proj (slot 3, bias add, row-major dst)
#define BM 128
#define BN 128
#define BK 32
#define NSTEP (D_MODEL / BK)            // 32
#define LDT 40                           // bf16 per smem row (32 + 8 pad)
#define LDTB (LDT * 2)                   // 80 bytes
#define TILE_BYTES (128 * LDTB)          // 10240
#define STAGE_BYTES (4 * TILE_BYTES)     // 40960: Ahi|Alo|Bhi|Blo
#define GEMM_SMEM (2 * STAGE_BYTES)      // 81920

__global__ __launch_bounds__(256) void mma_gemm(
    const __nv_bfloat16* __restrict__ Ahi,
    const __nv_bfloat16* __restrict__ Alo,
    const float* __restrict__ bias,
    float* __restrict__ outp,
    int mode)
{
    extern __shared__ char smem[];
    const int tid  = threadIdx.x;
    const int wid  = tid >> 5;
    const int lane = tid & 31;
    const int m0 = blockIdx.y * BM;
    const int n0 = blockIdx.x * BN;
    const int z  = blockIdx.z;

    const int wslot = (mode == 0) ? z : 3;
    const __nv_bfloat16* Bhi = g_wt_hi + (size_t)wslot * D_MODEL * D_MODEL;
    const __nv_bfloat16* Blo = g_wt_lo + (size_t)wslot * D_MODEL * D_MODEL;

    const uint32_t sbase = smem_u32(smem);

    float c[2][8][4];
#pragma unroll
    for (int i = 0; i < 2; i++)
#pragma unroll
        for (int j = 0; j < 8; j++)
#pragma unroll
            for (int k = 0; k < 4; k++) c[i][j][k] = 0.f;

    const int m_off = (wid & 3) * 32;     // warp rows within CTA tile
    const int n_off = (wid >> 2) * 64;    // warp cols within CTA tile

    // ldmatrix lane address components
    const uint32_t aLane = (uint32_t)((lane & 15) * LDTB + (lane >> 4) * 16);
    const uint32_t bLane = (uint32_t)(((lane & 7) + ((lane >> 4) & 1) * 8) * LDTB
                                      + ((lane >> 3) & 1) * 16);

    // async-load one BK stage into buffer `buf`
    auto load_stage = [&](int ks, int buf) {
        const int k0 = ks * BK;
        const uint32_t stage = sbase + buf * STAGE_BYTES;
#pragma unroll
        for (int o = 0; o < 8; o++) {
            int flat = o * 256 + tid;          // 0..2047
            int sel = flat >> 10;              // 0=A, 1=B
            int f   = flat & 1023;
            int hl  = f >> 9;                  // 0=hi, 1=lo
            int ff  = f & 511;
            int row = ff >> 2, ch = ff & 3;    // 128 rows x 4 x 16B
            const __nv_bfloat16* src = (sel == 0)
                ? (hl ? Alo : Ahi) + (size_t)(m0 + row) * D_MODEL + k0 + ch * 8
                : (hl ? Blo : Bhi) + (size_t)(n0 + row) * D_MODEL + k0 + ch * 8;
            uint32_t dst = stage + (uint32_t)(sel * (2 * TILE_BYTES) + hl * TILE_BYTES
                                              + row * LDTB + ch * 16);
            cpasync16(dst, src);
        }
        CP_COMMIT();
    };

    load_stage(0, 0);

#pragma unroll 1
    for (int ks = 0; ks < NSTEP; ks++) {
        const int buf = ks & 1;
        if (ks + 1 < NSTEP) { load_stage(ks + 1, buf ^ 1); CP_WAIT(1); }
        else                { CP_WAIT(0); }
        __syncthreads();

        const uint32_t st = sbase + buf * STAGE_BYTES;
        const uint32_t aBase = st + (uint32_t)(m_off * LDTB) + aLane;
        const uint32_t bBase = st + 2 * TILE_BYTES + (uint32_t)(n_off * LDTB) + bLane;

#pragma unroll
        for (int s16 = 0; s16 < 2; s16++) {
            uint32_t ah[2][4], al[2][4];
#pragma unroll
            for (int tm = 0; tm < 2; tm++) {
                ldm4(ah[tm], aBase + tm * 16 * LDTB + s16 * 32);
                ldm4(al[tm], aBase + TILE_BYTES + tm * 16 * LDTB + s16 * 32);
            }
#pragma unroll
            for (int tb = 0; tb < 4; tb++) {
                uint32_t bh[4], bl[4];
                ldm4(bh, bBase + tb * 16 * LDTB + s16 * 32);
                ldm4(bl, bBase + TILE_BYTES + tb * 16 * LDTB + s16 * 32);
#pragma unroll
                for (int hf = 0; hf < 2; hf++) {
                    const int tn = tb * 2 + hf;
#pragma unroll
                    for (int tm = 0; tm < 2; tm++) {
                        mma16816(c[tm][tn], ah[tm], bh[2 * hf], bh[2 * hf + 1]);
                        mma16816(c[tm][tn], ah[tm], bl[2 * hf], bl[2 * hf + 1]);
                        mma16816(c[tm][tn], al[tm], bh[2 * hf], bh[2 * hf + 1]);
                    }
                }
            }
        }
        __syncthreads();   // protect buffer before the next-next stage overwrites
    }

    // ---------------- epilogue: fragment -> global ---------------------------
    const int lrow = lane >> 2;
    const int lcol = (lane & 3) * 2;
    float* dstq = (mode == 0) ? ((z == 0) ? g_q : (z == 1) ? g_k : g_v) : outp;

#pragma unroll
    for (int tm = 0; tm < 2; tm++) {
#pragma unroll
        for (int tn = 0; tn < 8; tn++) {
            const int row0 = m0 + m_off + tm * 16 + lrow;
            const int col  = n0 + n_off + tn * 8 + lcol;
#pragma unroll
            for (int rr = 0; rr < 2; rr++) {
                const int row = row0 + rr * 8;
                float2 v = make_float2(c[tm][tn][rr * 2], c[tm][tn][rr * 2 + 1]);
                if (mode == 0) {
                    const int b = row >> 11, s = row & (SEQ - 1);
                    const int h = col >> 6, d = col & 63;
                    *(float2*)&dstq[((((size_t)b * NHEAD + h) * SEQ) + s) * HDIM + d] = v;
                } else {
                    v.x += bias[col];
                    v.y += bias[col + 1];
                    *(float2*)&dstq[(size_t)row * D_MODEL + col] = v;
                }
            }
        }
    }
}

// ---------------------------------------------------------------------------
// Flash attention (causal), fp32 — unchanged (known good, 7.8e-7 path).
// ---------------------------------------------------------------------------
#define LDP 68

__global__ __launch_bounds__(256, 2) void attn_kernel()
{
    extern __shared__ float smdyn[];
    float* Qs  = smdyn;
    float* KsT = Qs + 64 * LDP;
    float* Vs  = KsT + 64 * LDP;
    float* Ps  = Vs + 64 * LDP;
    float* red = Ps + 64 * LDP;
    float* mrow = red + 64 * 17;
    float* lrow = mrow + 64;

    const int qt = blockIdx.x;
    const int h  = blockIdx.y;
    const int b  = blockIdx.z;
    const int tid = threadIdx.x;
    const int tx = tid & 15;
    const int ty = tid >> 4;

    const size_t headrow = ((size_t)b * NHEAD + h) * SEQ;

#pragma unroll
    for (int i = 0; i < 4; i++) {
        int f = i * 256 + tid;
        int r = f >> 4, c4 = f & 15;
        *(float4*)&Qs[r * LDP + c4 * 4] =
            *(const float4*)&g_q[(headrow + (size_t)qt * 64 + r) * HDIM + c4 * 4];
    }
    if (tid < 64) { mrow[tid] = -1e30f; lrow[tid] = 0.f; }

    float O[4][4];
#pragma unroll
    for (int i = 0; i < 4; i++)
#pragma unroll
        for (int j = 0; j < 4; j++) O[i][j] = 0.f;

    for (int kt = 0; kt <= qt; kt++) {
        __syncthreads();

#pragma unroll
        for (int i = 0; i < 4; i++) {
            int f = i * 256 + tid;
            int r = f >> 4, c4 = f & 15;
            size_t grow = headrow + (size_t)kt * 64 + r;
            *(float4*)&Ps[r * LDP + c4 * 4] = *(const float4*)&g_k[grow * HDIM + c4 * 4];
            *(float4*)&Vs[r * LDP + c4 * 4] = *(const float4*)&g_v[grow * HDIM + c4 * 4];
        }
        __syncthreads();

        {
            int c = tid & 63, dg = tid >> 6;
#pragma unroll
            for (int dd = 0; dd < 16; dd++) {
                int d = dg * 16 + dd;
                KsT[d * LDP + c] = Ps[c * LDP + d];
            }
        }
        __syncthreads();

        float s[4][4];
#pragma unroll
        for (int i = 0; i < 4; i++)
#pragma unroll
            for (int j = 0; j < 4; j++) s[i][j] = 0.f;

#pragma unroll
        for (int d4 = 0; d4 < 16; d4++) {
            float qreg[4][4];
#pragma unroll
            for (int i = 0; i < 4; i++)
                *(float4*)&qreg[i][0] = *(float4*)&Qs[(ty * 4 + i) * LDP + d4 * 4];
#pragma unroll
            for (int dd = 0; dd < 4; dd++) {
                float kreg[4];
                *(float4*)&kreg[0] = *(float4*)&KsT[(d4 * 4 + dd) * LDP + tx * 4];
#pragma unroll
                for (int i = 0; i < 4; i++)
#pragma unroll
                    for (int j = 0; j < 4; j++)
                        s[i][j] = fmaf(qreg[i][dd], kreg[j], s[i][j]);
            }
        }

#pragma unroll
        for (int i = 0; i < 4; i++)
#pragma unroll
            for (int j = 0; j < 4; j++) s[i][j] *= 0.125f;
        if (kt == qt) {
#pragma unroll
            for (int i = 0; i < 4; i++)
#pragma unroll
                for (int j = 0; j < 4; j++)
                    if ((tx * 4 + j) > (ty * 4 + i)) s[i][j] = -1e30f;
        }

#pragma unroll
        for (int i = 0; i < 4; i++) {
            float lm = fmaxf(fmaxf(s[i][0], s[i][1]), fmaxf(s[i][2], s[i][3]));
            red[(ty * 4 + i) * 17 + tx] = lm;
        }
        __syncthreads();

        float nm[4], alpha[4], lsum[4];
#pragma unroll
        for (int i = 0; i < 4; i++) {
            int r = ty * 4 + i;
            float m = -1e30f;
#pragma unroll
            for (int t = 0; t < 16; t++) m = fmaxf(m, red[r * 17 + t]);
            float mo = mrow[r];
            nm[i] = fmaxf(mo, m);
            alpha[i] = __expf(mo - nm[i]);
            float sum = 0.f;
#pragma unroll
            for (int j = 0; j < 4; j++) {
                float p = __expf(s[i][j] - nm[i]);
                s[i][j] = p;
                sum += p;
            }
            lsum[i] = sum;
        }
        __syncthreads();

#pragma unroll
        for (int i = 0; i < 4; i++) {
            red[(ty * 4 + i) * 17 + tx] = lsum[i];
            *(float4*)&Ps[(ty * 4 + i) * LDP + tx * 4] = *(float4*)&s[i][0];
        }
        __syncthreads();

#pragma unroll
        for (int i = 0; i < 4; i++) {
            int r = ty * 4 + i;
            if (tx == 0) {
                float lt = 0.f;
#pragma unroll
                for (int t = 0; t < 16; t++) lt += red[r * 17 + t];
                lrow[r] = lrow[r] * alpha[i] + lt;
                mrow[r] = nm[i];
            }
#pragma unroll
            for (int j = 0; j < 4; j++) O[i][j] *= alpha[i];
        }

#pragma unroll
        for (int c4 = 0; c4 < 16; c4++) {
            float preg[4][4];
#pragma unroll
            for (int i = 0; i < 4; i++)
                *(float4*)&preg[i][0] = *(float4*)&Ps[(ty * 4 + i) * LDP + c4 * 4];
#pragma unroll
            for (int cc = 0; cc < 4; cc++) {
                float vreg[4];
                *(float4*)&vreg[0] = *(float4*)&Vs[(c4 * 4 + cc) * LDP + tx * 4];
#pragma unroll
                for (int i = 0; i < 4; i++)
#pragma unroll
                    for (int j = 0; j < 4; j++)
                        O[i][j] = fmaf(preg[i][cc], vreg[j], O[i][j]);
            }
        }
    }

    __syncthreads();

#pragma unroll
    for (int i = 0; i < 4; i++) {
        int r = ty * 4 + i;
        float inv = 1.f / lrow[r];
        float4 o;
        o.x = O[i][0] * inv; o.y = O[i][1] * inv;
        o.z = O[i][2] * inv; o.w = O[i][3] * inv;
        size_t srow = (size_t)b * SEQ + (size_t)qt * 64 + r;
        *(float4*)&g_ctx[srow * D_MODEL + h * 64 + tx * 4] = o;
    }
}

#define ATTN_SMEM ((4 * 64 * LDP + 64 * 17 + 128) * (int)sizeof(float))

// ---------------------------------------------------------------------------
extern "C" void kernel_launch(void* const* d_in, const int* in_sizes, int n_in,
                              void* d_out, int out_size)
{
    const float* x  = (const float*)d_in[0];
    const float* wq = (const float*)d_in[1];
    const float* wk = (const float*)d_in[2];
    const float* wv = (const float*)d_in[3];
    const float* wo = (const float*)d_in[4];
    const float* bo = (const float*)d_in[5];
    float* out = (float*)d_out;

    cudaFuncSetAttribute(mma_gemm, cudaFuncAttributeMaxDynamicSharedMemorySize, GEMM_SMEM);
    cudaFuncSetAttribute(attn_kernel, cudaFuncAttributeMaxDynamicSharedMemorySize, ATTN_SMEM);

    // resolve device-global scratch addresses every call (no static caching)
    __nv_bfloat16 *xhi, *xlo, *chi, *clo;
    float* ctxp;
    cudaGetSymbolAddress((void**)&xhi, g_xhi);
    cudaGetSymbolAddress((void**)&xlo, g_xlo);
    cudaGetSymbolAddress((void**)&chi, g_chi);
    cudaGetSymbolAddress((void**)&clo, g_clo);
    cudaGetSymbolAddress((void**)&ctxp, g_ctx);

    const int NTOT = BATCH * SEQ * D_MODEL;                 // 4194304
    conv_split<<<NTOT / (256 * 4), 256>>>(x, xhi, xlo);
    conv_wt<<<dim3(32, 32, 4), dim3(32, 8)>>>(wq, wk, wv, wo);
    mma_gemm<<<dim3(8, 32, 3), 256, GEMM_SMEM>>>(xhi, xlo, nullptr, nullptr, 0);
    attn_kernel<<<dim3(32, NHEAD, BATCH), 256, ATTN_SMEM>>>();
    conv_split<<<NTOT / (256 * 4), 256>>>(ctxp, chi, clo);
    mma_gemm<<<dim3(8, 32, 1), 256, GEMM_SMEM>>>(chi, clo, bo, out, 1);
}